// round 4
// baseline (speedup 1.0000x reference)
#include <cuda_runtime.h>
#include <math.h>

#define Sq  2048
#define Dd  512
#define Hh  8
#define DHh 64
#define CWw 128

// ---------------- scratch (device globals) -------------------------------------
__device__ float g_cur[Sq * Dd];
__device__ float g_q[Sq * DHh];
__device__ float g_k[Sq * DHh];
__device__ float g_v[Sq * DHh];
__device__ float g_delta[Sq * DHh];

// ---------------- cp.async helpers ----------------------------------------------
__device__ __forceinline__ unsigned smem_u32(const void* p) {
    return (unsigned)__cvta_generic_to_shared(p);
}
__device__ __forceinline__ void cp_async16(void* dst, const void* src) {
    asm volatile("cp.async.ca.shared.global [%0], [%1], 16;\n"
                 :: "r"(smem_u32(dst)), "l"(src));
}
#define CP_COMMIT() asm volatile("cp.async.commit_group;\n")
#define CP_WAIT(N)  asm volatile("cp.async.wait_group %0;\n" :: "n"(N))

// ---------------- init: cur = x -------------------------------------------------
__global__ void init_kernel(const float4* __restrict__ x) {
    int i = blockIdx.x * blockDim.x + threadIdx.x;
    ((float4*)g_cur)[i] = x[i];
}

// ---------------- qkv GEMM: 32x64 tile, BK=64, 128 threads, 4x4 microtile -------
__global__ __launch_bounds__(128) void qkv_gemm(const float* __restrict__ Wq,
                                                const float* __restrict__ Wk,
                                                const float* __restrict__ Wvd, int h)
{
    __shared__ float Xs[64][36];   // [k][m]
    __shared__ float Ws[64][68];   // [k][n]

    const int sel = blockIdx.y;
    const float* B = (sel == 0 ? Wq : sel == 1 ? Wk : Wvd) + (size_t)h * DHh * Dd;
    float* C = (sel == 0 ? g_q : sel == 1 ? g_k : g_v);
    const int m0 = blockIdx.x * 32;

    const int t  = threadIdx.x;    // 128
    const int tx = t & 15;         // n4
    const int ty = t >> 4;         // m4

    float acc[4][4] = {};

    for (int k0 = 0; k0 < Dd; k0 += 64) {
        #pragma unroll
        for (int r = 0; r < 4; r++) {          // A: 32 rows x 16 f4
            int f = t + r * 128;
            int m = f >> 4, kv = f & 15;
            float4 va = *(const float4*)&g_cur[(size_t)(m0 + m) * Dd + k0 + kv * 4];
            Xs[kv * 4 + 0][m] = va.x;
            Xs[kv * 4 + 1][m] = va.y;
            Xs[kv * 4 + 2][m] = va.z;
            Xs[kv * 4 + 3][m] = va.w;
        }
        #pragma unroll
        for (int r = 0; r < 8; r++) {          // B: 64 rows x 16 f4
            int f = t + r * 128;
            int n = f >> 4, kv = f & 15;
            float4 vb = *(const float4*)&B[(size_t)n * Dd + k0 + kv * 4];
            Ws[kv * 4 + 0][n] = vb.x;
            Ws[kv * 4 + 1][n] = vb.y;
            Ws[kv * 4 + 2][n] = vb.z;
            Ws[kv * 4 + 3][n] = vb.w;
        }
        __syncthreads();

        #pragma unroll
        for (int k = 0; k < 64; k++) {
            float4 a4 = *(const float4*)&Xs[k][ty * 4];
            float4 b4 = *(const float4*)&Ws[k][tx * 4];
            float a[4] = {a4.x, a4.y, a4.z, a4.w};
            float b[4] = {b4.x, b4.y, b4.z, b4.w};
            #pragma unroll
            for (int i = 0; i < 4; i++)
                #pragma unroll
                for (int j = 0; j < 4; j++)
                    acc[i][j] = fmaf(a[i], b[j], acc[i][j]);
        }
        __syncthreads();
    }

    #pragma unroll
    for (int i = 0; i < 4; i++) {
        float4 o = make_float4(acc[i][0], acc[i][1], acc[i][2], acc[i][3]);
        *(float4*)&C[(size_t)(m0 + ty * 4 + i) * DHh + tx * 4] = o;
    }
}

// ---------------- flash-style windowed attention --------------------------------
// block = 16 queries; single K/V buffer (K, then V) -> 101KB smem, 2 blocks/SM
#define KEXT 288
#define KP   68
#define PP   292

__global__ __launch_bounds__(256) void attn_flash()
{
    extern __shared__ float sm[];
    float* KV = sm;                         // [288][68]: first K, then V
    float* Ps = sm + KEXT * KP;             // [16][292]
    float* Qs = Ps + 16 * PP;               // [16][64]
    float* Rs = sm;                         // AV partials (after V consumed)

    const int t  = threadIdx.x;             // 256
    const int j0 = blockIdx.x * 16;
    const int kb = j0 - CWw;

    // ---- load K window + Q
    for (int f = t; f < KEXT * 16; f += 256) {
        int kk = f >> 4, d4 = f & 15;
        int gk = kb + kk;
        float4 kv = make_float4(0.f, 0.f, 0.f, 0.f);
        if (gk >= 0 && gk < Sq) kv = ((const float4*)&g_k[(size_t)gk * DHh])[d4];
        *(float4*)&KV[kk * KP + d4 * 4] = kv;
    }
    {
        int q = t >> 4, d4 = t & 15;
        ((float4*)&Qs[q * DHh])[d4] = ((const float4*)&g_q[(size_t)(j0 + q) * DHh])[d4];
    }
    __syncthreads();

    const int w    = t >> 5;
    const int lane = t & 31;

    // ---- scores: warp w owns queries 2w, 2w+1
    const int q0 = 2 * w, q1 = 2 * w + 1;
    float a0[9] = {}, a1[9] = {};
    #pragma unroll
    for (int d4 = 0; d4 < 16; d4++) {
        float4 qa = *(const float4*)&Qs[q0 * DHh + d4 * 4];
        float4 qb = *(const float4*)&Qs[q1 * DHh + d4 * 4];
        #pragma unroll
        for (int jj = 0; jj < 9; jj++) {
            const float4 kv = *(const float4*)&KV[(lane + 32 * jj) * KP + d4 * 4];
            a0[jj] = fmaf(kv.x, qa.x, fmaf(kv.y, qa.y, fmaf(kv.z, qa.z, fmaf(kv.w, qa.w, a0[jj]))));
            a1[jj] = fmaf(kv.x, qb.x, fmaf(kv.y, qb.y, fmaf(kv.z, qb.z, fmaf(kv.w, qb.w, a1[jj]))));
        }
    }

    float m0 = -1e30f, m1 = -1e30f;
    #pragma unroll
    for (int jj = 0; jj < 9; jj++) {
        int kk = lane + 32 * jj;
        int gk = kb + kk;
        bool gok = (gk >= 0) && (gk < Sq);
        bool v0 = gok && (kk >= q0) && (kk < q0 + 256);
        bool v1 = gok && (kk >= q1) && (kk < q1 + 256);
        a0[jj] = v0 ? a0[jj] * 0.125f : -1e30f;
        a1[jj] = v1 ? a1[jj] * 0.125f : -1e30f;
        m0 = fmaxf(m0, a0[jj]);
        m1 = fmaxf(m1, a1[jj]);
    }
    #pragma unroll
    for (int o = 16; o; o >>= 1) {
        m0 = fmaxf(m0, __shfl_xor_sync(0xffffffffu, m0, o));
        m1 = fmaxf(m1, __shfl_xor_sync(0xffffffffu, m1, o));
    }
    float s0 = 0.f, s1 = 0.f;
    #pragma unroll
    for (int jj = 0; jj < 9; jj++) {
        a0[jj] = __expf(a0[jj] - m0);
        a1[jj] = __expf(a1[jj] - m1);
        s0 += a0[jj];
        s1 += a1[jj];
    }
    #pragma unroll
    for (int o = 16; o; o >>= 1) {
        s0 += __shfl_xor_sync(0xffffffffu, s0, o);
        s1 += __shfl_xor_sync(0xffffffffu, s1, o);
    }
    const float i0 = 1.f / s0, i1 = 1.f / s1;
    #pragma unroll
    for (int jj = 0; jj < 9; jj++) {
        Ps[q0 * PP + lane + 32 * jj] = a0[jj] * i0;
        Ps[q1 * PP + lane + 32 * jj] = a1[jj] * i1;
    }
    __syncthreads();

    // ---- overwrite K buffer with V window
    for (int f = t; f < KEXT * 16; f += 256) {
        int kk = f >> 4, d4 = f & 15;
        int gk = kb + kk;
        float4 vv = make_float4(0.f, 0.f, 0.f, 0.f);
        if (gk >= 0 && gk < Sq) vv = ((const float4*)&g_v[(size_t)gk * DHh])[d4];
        *(float4*)&KV[kk * KP + d4 * 4] = vv;
    }
    __syncthreads();

    // ---- AV: warp w owns keys [36w, 36w+36)
    const int qh = (lane >> 4) * 8;
    const int d4 = lane & 15;
    float4 r[8] = {};
    for (int i = 0; i < 36; i++) {
        int kk = w * 36 + i;
        float4 v4 = *(const float4*)&KV[kk * KP + d4 * 4];
        #pragma unroll
        for (int qi = 0; qi < 8; qi++) {
            float p = Ps[(qh + qi) * PP + kk];
            r[qi].x = fmaf(p, v4.x, r[qi].x);
            r[qi].y = fmaf(p, v4.y, r[qi].y);
            r[qi].z = fmaf(p, v4.z, r[qi].z);
            r[qi].w = fmaf(p, v4.w, r[qi].w);
        }
    }
    __syncthreads();   // all V reads done before overlaying partials

    #pragma unroll
    for (int qi = 0; qi < 8; qi++)
        *(float4*)&Rs[(w * 16 + qh + qi) * DHh + d4 * 4] = r[qi];
    __syncthreads();

    #pragma unroll
    for (int ii = 0; ii < 4; ii++) {
        int idx = t + 256 * ii;
        int q = idx >> 6, d = idx & 63;
        float s = 0.f;
        #pragma unroll
        for (int ww = 0; ww < 8; ww++) s += Rs[(ww * 16 + q) * DHh + d];
        g_delta[(size_t)(j0 + q) * DHh + d] = s;
    }
}

// ---------------- fused up-projection + residual + renorm -----------------------
// 128 threads, 16 tokens/block; W streamed in 4 n-chunks of 128 rows [n][k],
// cp.async double-buffered. Warp owns 4 tokens, lane owns 4 n per chunk.
#define WCP 68                       // chunk row pitch (17 f4, odd -> conflict-free)
#define WCHUNK (128 * WCP)           // floats per chunk buffer

__global__ __launch_bounds__(128) void upnorm_kernel(const float* __restrict__ Wvu,
                                                     int h, int last,
                                                     float* __restrict__ out)
{
    extern __shared__ float sm[];
    float* Wc[2] = { sm, sm + WCHUNK };
    float* As = sm + 2 * WCHUNK;     // [16][64]

    const int t    = threadIdx.x;    // 128
    const int w    = t >> 5;         // 0..3
    const int lane = t & 31;
    const int m0   = blockIdx.x * 16;
    const float* W = Wvu + (size_t)h * Dd * DHh;

    // delta tile (16 x 64)
    #pragma unroll
    for (int r = 0; r < 2; r++) {
        int f = t + r * 128;
        int m = f >> 4, k4 = f & 15;
        *(float4*)&As[m * DHh + k4 * 4] =
            ((const float4*)&g_delta[(size_t)(m0 + m) * DHh])[k4];
    }

    // stage chunk 0
    #pragma unroll
    for (int r = 0; r < 16; r++) {
        int f = t + r * 128;
        int row = f >> 4, k4 = f & 15;
        cp_async16(&Wc[0][row * WCP + k4 * 4], &W[(size_t)row * DHh + k4 * 4]);
    }
    CP_COMMIT();

    float acc[4][16] = {};

    for (int c = 0; c < 4; c++) {
        if (c < 3) {
            float* dst = Wc[(c + 1) & 1];
            const float* src = W + (size_t)(c + 1) * 128 * DHh;
            #pragma unroll
            for (int r = 0; r < 16; r++) {
                int f = t + r * 128;
                int row = f >> 4, k4 = f & 15;
                cp_async16(&dst[row * WCP + k4 * 4], &src[(size_t)row * DHh + k4 * 4]);
            }
            CP_COMMIT();
            CP_WAIT(1);
        } else {
            CP_WAIT(0);
        }
        __syncthreads();

        const float* Wb = Wc[c & 1];
        #pragma unroll
        for (int k4 = 0; k4 < 16; k4++) {
            float4 a[4], wv[4];
            #pragma unroll
            for (int i = 0; i < 4; i++)
                a[i] = *(const float4*)&As[(4 * w + i) * DHh + k4 * 4];
            #pragma unroll
            for (int r = 0; r < 4; r++)
                wv[r] = *(const float4*)&Wb[(lane + 32 * r) * WCP + k4 * 4];
            #pragma unroll
            for (int i = 0; i < 4; i++)
                #pragma unroll
                for (int r = 0; r < 4; r++) {
                    float s = acc[i][c * 4 + r];
                    s = fmaf(a[i].x, wv[r].x, s);
                    s = fmaf(a[i].y, wv[r].y, s);
                    s = fmaf(a[i].z, wv[r].z, s);
                    s = fmaf(a[i].w, wv[r].w, s);
                    acc[i][c * 4 + r] = s;
                }
        }
        __syncthreads();
    }

    // residual + renorm per token (warp-local; lane covers 16 of 512 columns)
    #pragma unroll
    for (int i = 0; i < 4; i++) {
        const int m = m0 + 4 * w + i;
        float cres[16], y[16];
        float s = 0.f;
        #pragma unroll
        for (int j = 0; j < 16; j++) {
            int n = (j >> 2) * 128 + lane + 32 * (j & 3);
            cres[j] = g_cur[(size_t)m * Dd + n];
            y[j] = acc[i][j] + cres[j];
            s += y[j];
        }
        #pragma unroll
        for (int o = 16; o; o >>= 1) s += __shfl_xor_sync(0xffffffffu, s, o);
        float im = 512.f / s;                      // 1/m1
        s = 0.f;
        #pragma unroll
        for (int j = 0; j < 16; j++) { y[j] *= im; s += y[j]; }
        #pragma unroll
        for (int o = 16; o; o >>= 1) s += __shfl_xor_sync(0xffffffffu, s, o);
        float m2 = s * (1.f / 512.f);
        float v = 0.f;
        #pragma unroll
        for (int j = 0; j < 16; j++) { y[j] -= m2; v += y[j] * y[j]; }
        #pragma unroll
        for (int o = 16; o; o >>= 1) v += __shfl_xor_sync(0xffffffffu, v, o);
        float is = rsqrtf(v * (1.f / 511.f));

        #pragma unroll
        for (int j = 0; j < 16; j++) {
            int n = (j >> 2) * 128 + lane + 32 * (j & 3);
            float nv = cres[j] + y[j] * is + m2;
            g_cur[(size_t)m * Dd + n] = nv;
            if (last) out[(size_t)m * Dd + n] = nv * 0.125f;
        }
    }
}

// ---------------- launch ---------------------------------------------------------
extern "C" void kernel_launch(void* const* d_in, const int* in_sizes, int n_in,
                              void* d_out, int out_size)
{
    const float* x   = (const float*)d_in[0];
    const float* Wq  = (const float*)d_in[1];
    const float* Wk  = (const float*)d_in[2];
    const float* Wvd = (const float*)d_in[3];
    const float* Wvu = (const float*)d_in[4];
    float* out = (float*)d_out;

    const int attn_smem = (KEXT * KP + 16 * PP + 16 * DHh) * 4;     // 101120 B
    const int up_smem   = (2 * WCHUNK + 16 * DHh) * 4;              // 73728 B
    cudaFuncSetAttribute(attn_flash, cudaFuncAttributeMaxDynamicSharedMemorySize, attn_smem);
    cudaFuncSetAttribute(upnorm_kernel, cudaFuncAttributeMaxDynamicSharedMemorySize, up_smem);

    init_kernel<<<(Sq * Dd / 4) / 256, 256>>>((const float4*)x);
    for (int h = 0; h < Hh; h++) {
        qkv_gemm<<<dim3(Sq / 32, 3), 128>>>(Wq, Wk, Wvd, h);
        attn_flash<<<Sq / 16, 256, attn_smem>>>();
        upnorm_kernel<<<Sq / 16, 128, up_smem>>>(Wvu, h, h == Hh - 1 ? 1 : 0, out);
    }
}

// round 5
// speedup vs baseline: 1.1043x; 1.1043x over previous
#include <cuda_runtime.h>
#include <math.h>

#define Sq  2048
#define Dd  512
#define Hh  8
#define DHh 64
#define CWw 128

// ---------------- scratch (device globals) -------------------------------------
__device__ float g_cur[Sq * Dd];
__device__ float g_q[Sq * DHh];
__device__ float g_k[Sq * DHh];
__device__ float g_v[Sq * DHh];

// ---------------- cp.async helpers ----------------------------------------------
__device__ __forceinline__ unsigned smem_u32(const void* p) {
    return (unsigned)__cvta_generic_to_shared(p);
}
__device__ __forceinline__ void cp_async16(void* dst, const void* src) {
    asm volatile("cp.async.ca.shared.global [%0], [%1], 16;\n"
                 :: "r"(smem_u32(dst)), "l"(src));
}
#define CP_COMMIT() asm volatile("cp.async.commit_group;\n")
#define CP_WAIT(N)  asm volatile("cp.async.wait_group %0;\n" :: "n"(N))

// ---------------- init: cur = x -------------------------------------------------
__global__ void init_kernel(const float4* __restrict__ x) {
    int i = blockIdx.x * blockDim.x + threadIdx.x;
    ((float4*)g_cur)[i] = x[i];
}

// ---------------- qkv GEMM: 32x64 tile, 128 threads, 4x4 microtile (R3 proven) --
__global__ __launch_bounds__(128) void qkv_gemm(const float* __restrict__ Wq,
                                                const float* __restrict__ Wk,
                                                const float* __restrict__ Wvd, int h)
{
    __shared__ float Xs[32][36];   // [k][m]
    __shared__ float Ws[32][68];   // [k][n]

    const int sel = blockIdx.y;
    const float* B = (sel == 0 ? Wq : sel == 1 ? Wk : Wvd) + (size_t)h * DHh * Dd;
    float* C = (sel == 0 ? g_q : sel == 1 ? g_k : g_v);
    const int m0 = blockIdx.x * 32;

    const int t  = threadIdx.x;    // 128
    const int tx = t & 15;
    const int ty = t >> 4;

    float acc[4][4] = {};

    for (int k0 = 0; k0 < Dd; k0 += 32) {
        #pragma unroll
        for (int r = 0; r < 2; r++) {
            int f = t + r * 128;
            int m = f >> 3, kv = f & 7;
            float4 va = *(const float4*)&g_cur[(size_t)(m0 + m) * Dd + k0 + kv * 4];
            Xs[kv * 4 + 0][m] = va.x;
            Xs[kv * 4 + 1][m] = va.y;
            Xs[kv * 4 + 2][m] = va.z;
            Xs[kv * 4 + 3][m] = va.w;
        }
        #pragma unroll
        for (int r = 0; r < 4; r++) {
            int f = t + r * 128;
            int n = f >> 3, kv = f & 7;
            float4 vb = *(const float4*)&B[(size_t)n * Dd + k0 + kv * 4];
            Ws[kv * 4 + 0][n] = vb.x;
            Ws[kv * 4 + 1][n] = vb.y;
            Ws[kv * 4 + 2][n] = vb.z;
            Ws[kv * 4 + 3][n] = vb.w;
        }
        __syncthreads();

        #pragma unroll
        for (int k = 0; k < 32; k++) {
            float4 a4 = *(const float4*)&Xs[k][ty * 4];
            float4 b4 = *(const float4*)&Ws[k][tx * 4];
            float a[4] = {a4.x, a4.y, a4.z, a4.w};
            float b[4] = {b4.x, b4.y, b4.z, b4.w};
            #pragma unroll
            for (int i = 0; i < 4; i++)
                #pragma unroll
                for (int j = 0; j < 4; j++)
                    acc[i][j] = fmaf(a[i], b[j], acc[i][j]);
        }
        __syncthreads();
    }

    #pragma unroll
    for (int i = 0; i < 4; i++) {
        float4 o = make_float4(acc[i][0], acc[i][1], acc[i][2], acc[i][3]);
        *(float4*)&C[(size_t)(m0 + ty * 4 + i) * DHh + tx * 4] = o;
    }
}

// ---------------- fused attn + up-projection + residual + renorm ----------------
// block = 16 tokens, 256 threads. smem regions:
//   A: 19584 floats -> Ks[288][68]  / later AV partials Rs[8][16][64] / later W chunks (2 x 128x68)
//   B: Ps[16][293]
//   C: Qs[16][64]
//   D: ds[16][64]
#define KEXT 288
#define KP   68
#define PP   293
#define WCP  68
#define WCHUNK (128 * WCP)          // 8704 floats per W chunk buffer

#define SM_A   0
#define SM_PS  (KEXT * KP)          // 19584
#define SM_QS  (SM_PS + 16 * PP)    // 24272
#define SM_DS  (SM_QS + 16 * DHh)   // 25296
#define SM_TOT (SM_DS + 16 * DHh)   // 26320 floats = 105280 B

__global__ __launch_bounds__(256) void attn_upnorm(const float* __restrict__ Wvu,
                                                   int h, int last,
                                                   float* __restrict__ out)
{
    extern __shared__ float sm[];
    float* Ks = sm + SM_A;
    float* Ps = sm + SM_PS;
    float* Qs = sm + SM_QS;
    float* ds = sm + SM_DS;
    float* Rs = sm + SM_A;                  // partials (after Ks consumed)
    float* Wc[2] = { sm + SM_A, sm + SM_A + WCHUNK };

    const int t    = threadIdx.x;           // 256
    const int w    = t >> 5;
    const int lane = t & 31;
    const int j0   = blockIdx.x * 16;
    const int kb   = j0 - CWw;
    const float* W = Wvu + (size_t)h * Dd * DHh;

    // ---- load K window + Q
    for (int f = t; f < KEXT * 16; f += 256) {
        int kk = f >> 4, d4 = f & 15;
        int gk = kb + kk;
        float4 kv = make_float4(0.f, 0.f, 0.f, 0.f);
        if (gk >= 0 && gk < Sq) kv = ((const float4*)&g_k[(size_t)gk * DHh])[d4];
        *(float4*)&Ks[kk * KP + d4 * 4] = kv;
    }
    {
        int q = t >> 4, d4 = t & 15;
        ((float4*)&Qs[q * DHh])[d4] = ((const float4*)&g_q[(size_t)(j0 + q) * DHh])[d4];
    }
    __syncthreads();

    // ---- scores: warp w owns queries q0=2w, q1=2w+1; lane owns kk = lane+32*jj
    const int q0 = 2 * w, q1 = 2 * w + 1;
    {
        float a0[9] = {}, a1[9] = {};
        #pragma unroll
        for (int d4 = 0; d4 < 16; d4++) {
            float4 qa = *(const float4*)&Qs[q0 * DHh + d4 * 4];
            float4 qb = *(const float4*)&Qs[q1 * DHh + d4 * 4];
            #pragma unroll
            for (int jj = 0; jj < 9; jj++) {
                const float4 kv = *(const float4*)&Ks[(lane + 32 * jj) * KP + d4 * 4];
                a0[jj] = fmaf(kv.x, qa.x, fmaf(kv.y, qa.y, fmaf(kv.z, qa.z, fmaf(kv.w, qa.w, a0[jj]))));
                a1[jj] = fmaf(kv.x, qb.x, fmaf(kv.y, qb.y, fmaf(kv.z, qb.z, fmaf(kv.w, qb.w, a1[jj]))));
            }
        }
        float m0 = -1e30f, m1 = -1e30f;
        #pragma unroll
        for (int jj = 0; jj < 9; jj++) {
            int kk = lane + 32 * jj;
            int gk = kb + kk;
            bool gok = (gk >= 0) && (gk < Sq);
            bool v0 = gok && (kk >= q0) && (kk < q0 + 256);
            bool v1 = gok && (kk >= q1) && (kk < q1 + 256);
            a0[jj] = v0 ? a0[jj] * 0.125f : -1e30f;
            a1[jj] = v1 ? a1[jj] * 0.125f : -1e30f;
            m0 = fmaxf(m0, a0[jj]);
            m1 = fmaxf(m1, a1[jj]);
        }
        #pragma unroll
        for (int o = 16; o; o >>= 1) {
            m0 = fmaxf(m0, __shfl_xor_sync(0xffffffffu, m0, o));
            m1 = fmaxf(m1, __shfl_xor_sync(0xffffffffu, m1, o));
        }
        float s0 = 0.f, s1 = 0.f;
        #pragma unroll
        for (int jj = 0; jj < 9; jj++) {
            a0[jj] = __expf(a0[jj] - m0);
            a1[jj] = __expf(a1[jj] - m1);
            s0 += a0[jj];
            s1 += a1[jj];
        }
        #pragma unroll
        for (int o = 16; o; o >>= 1) {
            s0 += __shfl_xor_sync(0xffffffffu, s0, o);
            s1 += __shfl_xor_sync(0xffffffffu, s1, o);
        }
        const float i0 = 1.f / s0, i1 = 1.f / s1;
        #pragma unroll
        for (int jj = 0; jj < 9; jj++) {
            Ps[q0 * PP + lane + 32 * jj] = a0[jj] * i0;
            Ps[q1 * PP + lane + 32 * jj] = a1[jj] * i1;
        }
    }
    __syncthreads();   // Ps complete; Ks no longer needed

    // ---- AV: warp w owns keys [36w, 36w+36); V read from gmem (L2-resident)
    {
        const int qh = (lane >> 4) * 8;
        const int d4 = lane & 15;
        float4 r[8] = {};
        for (int i = 0; i < 36; i++) {
            int kk = w * 36 + i;
            int gk = kb + kk;
            float4 v4 = make_float4(0.f, 0.f, 0.f, 0.f);
            if (gk >= 0 && gk < Sq)
                v4 = ((const float4*)&g_v[(size_t)gk * DHh])[d4];
            #pragma unroll
            for (int qi = 0; qi < 8; qi++) {
                float p = Ps[(qh + qi) * PP + kk];
                r[qi].x = fmaf(p, v4.x, r[qi].x);
                r[qi].y = fmaf(p, v4.y, r[qi].y);
                r[qi].z = fmaf(p, v4.z, r[qi].z);
                r[qi].w = fmaf(p, v4.w, r[qi].w);
            }
        }
        // write warp partials into region A (Ks dead)
        #pragma unroll
        for (int qi = 0; qi < 8; qi++)
            *(float4*)&Rs[(w * 16 + qh + qi) * DHh + d4 * 4] = r[qi];
    }
    __syncthreads();

    // reduce 8 warp-partials -> ds (16 x 64)
    #pragma unroll
    for (int ii = 0; ii < 4; ii++) {
        int idx = t + 256 * ii;
        int q = idx >> 6, d = idx & 63;
        float s = 0.f;
        #pragma unroll
        for (int ww = 0; ww < 8; ww++) s += Rs[(ww * 16 + q) * DHh + d];
        ds[q * DHh + d] = s;
    }
    __syncthreads();   // ds complete; Rs (region A) free for W chunks

    // ---- up-projection: stream W in 4 chunks of 128 rows, cp.async double-buffer
    #pragma unroll
    for (int r = 0; r < 8; r++) {
        int f = t + r * 256;
        int row = f >> 4, k4 = f & 15;
        cp_async16(&Wc[0][row * WCP + k4 * 4], &W[(size_t)row * DHh + k4 * 4]);
    }
    CP_COMMIT();

    float acc[2][16] = {};   // 2 tokens (2w, 2w+1), 16 n-columns total

    for (int c = 0; c < 4; c++) {
        if (c < 3) {
            float* dst = Wc[(c + 1) & 1];
            const float* src = W + (size_t)(c + 1) * 128 * DHh;
            #pragma unroll
            for (int r = 0; r < 8; r++) {
                int f = t + r * 256;
                int row = f >> 4, k4 = f & 15;
                cp_async16(&dst[row * WCP + k4 * 4], &src[(size_t)row * DHh + k4 * 4]);
            }
            CP_COMMIT();
            CP_WAIT(1);
        } else {
            CP_WAIT(0);
        }
        __syncthreads();

        const float* Wb = Wc[c & 1];
        #pragma unroll
        for (int k4 = 0; k4 < 16; k4++) {
            float4 a0 = *(const float4*)&ds[(2 * w + 0) * DHh + k4 * 4];
            float4 a1 = *(const float4*)&ds[(2 * w + 1) * DHh + k4 * 4];
            #pragma unroll
            for (int r = 0; r < 4; r++) {
                float4 wv = *(const float4*)&Wb[(lane + 32 * r) * WCP + k4 * 4];
                float s0 = acc[0][c * 4 + r];
                s0 = fmaf(a0.x, wv.x, s0);
                s0 = fmaf(a0.y, wv.y, s0);
                s0 = fmaf(a0.z, wv.z, s0);
                s0 = fmaf(a0.w, wv.w, s0);
                acc[0][c * 4 + r] = s0;
                float s1 = acc[1][c * 4 + r];
                s1 = fmaf(a1.x, wv.x, s1);
                s1 = fmaf(a1.y, wv.y, s1);
                s1 = fmaf(a1.z, wv.z, s1);
                s1 = fmaf(a1.w, wv.w, s1);
                acc[1][c * 4 + r] = s1;
            }
        }
        __syncthreads();
    }

    // ---- residual + renorm, 2 tokens per warp (warp-local)
    #pragma unroll
    for (int i = 0; i < 2; i++) {
        const int m = j0 + 2 * w + i;
        float cres[16], y[16];
        float s = 0.f;
        #pragma unroll
        for (int j = 0; j < 16; j++) {
            int n = (j >> 2) * 128 + lane + 32 * (j & 3);
            cres[j] = g_cur[(size_t)m * Dd + n];
            y[j] = acc[i][j] + cres[j];
            s += y[j];
        }
        #pragma unroll
        for (int o = 16; o; o >>= 1) s += __shfl_xor_sync(0xffffffffu, s, o);
        float im = 512.f / s;                       // 1/m1
        s = 0.f;
        #pragma unroll
        for (int j = 0; j < 16; j++) { y[j] *= im; s += y[j]; }
        #pragma unroll
        for (int o = 16; o; o >>= 1) s += __shfl_xor_sync(0xffffffffu, s, o);
        float m2 = s * (1.f / 512.f);
        float v = 0.f;
        #pragma unroll
        for (int j = 0; j < 16; j++) { y[j] -= m2; v += y[j] * y[j]; }
        #pragma unroll
        for (int o = 16; o; o >>= 1) v += __shfl_xor_sync(0xffffffffu, v, o);
        float is = rsqrtf(v * (1.f / 511.f));

        #pragma unroll
        for (int j = 0; j < 16; j++) {
            int n = (j >> 2) * 128 + lane + 32 * (j & 3);
            float nv = cres[j] + y[j] * is + m2;
            g_cur[(size_t)m * Dd + n] = nv;
            if (last) out[(size_t)m * Dd + n] = nv * 0.125f;
        }
    }
}

// ---------------- launch ---------------------------------------------------------
extern "C" void kernel_launch(void* const* d_in, const int* in_sizes, int n_in,
                              void* d_out, int out_size)
{
    const float* x   = (const float*)d_in[0];
    const float* Wq  = (const float*)d_in[1];
    const float* Wk  = (const float*)d_in[2];
    const float* Wvd = (const float*)d_in[3];
    const float* Wvu = (const float*)d_in[4];
    float* out = (float*)d_out;

    const int fused_smem = SM_TOT * 4;   // 105280 B
    cudaFuncSetAttribute(attn_upnorm, cudaFuncAttributeMaxDynamicSharedMemorySize, fused_smem);

    init_kernel<<<(Sq * Dd / 4) / 256, 256>>>((const float4*)x);
    for (int h = 0; h < Hh; h++) {
        qkv_gemm<<<dim3(Sq / 32, 3), 128>>>(Wq, Wk, Wvd, h);
        attn_upnorm<<<Sq / 16, 256, fused_smem>>>(Wvu, h, h == Hh - 1 ? 1 : 0, out);
    }
}

// round 6
// speedup vs baseline: 1.3966x; 1.2647x over previous
#include <cuda_runtime.h>
#include <math.h>

#define Sq  2048
#define Dd  512
#define Hh  8
#define DHh 64
#define CWw 128
#define NSPLIT 4
#define KSPL (Dd / NSPLIT)    // 128

// ---------------- scratch (device globals) -------------------------------------
__device__ float g_cur[Sq * Dd];
__device__ float g_q[Sq * DHh];
__device__ float g_k[Sq * DHh];
__device__ float g_v[Sq * DHh];
__device__ float g_delta[Sq * DHh];
__device__ float g_part[3][NSPLIT][Sq * DHh];   // split-K partials (6 MB)

// ---------------- init: cur = x -------------------------------------------------
__global__ void init_kernel(const float4* __restrict__ x) {
    int i = blockIdx.x * blockDim.x + threadIdx.x;
    ((float4*)g_cur)[i] = x[i];
}

// ---------------- qkv split-K partial GEMM --------------------------------------
// grid (S/32, 3, NSPLIT); block 128. C_part = cur[m, ks:ks+128] @ W[n, ks:ks+128]^T
__global__ __launch_bounds__(128) void qkv_partial(const float* __restrict__ Wq,
                                                   const float* __restrict__ Wk,
                                                   const float* __restrict__ Wvd, int h)
{
    __shared__ float Xs[32][36];   // [k][m]
    __shared__ float Ws[32][68];   // [k][n]

    const int sel = blockIdx.y;
    const int sp  = blockIdx.z;
    const float* B = (sel == 0 ? Wq : sel == 1 ? Wk : Wvd) + (size_t)h * DHh * Dd;
    float* C = &g_part[sel][sp][0];
    const int m0 = blockIdx.x * 32;
    const int kb = sp * KSPL;

    const int t  = threadIdx.x;
    const int tx = t & 15;
    const int ty = t >> 4;

    float acc[4][4] = {};

    for (int k0 = kb; k0 < kb + KSPL; k0 += 32) {
        #pragma unroll
        for (int r = 0; r < 2; r++) {
            int f = t + r * 128;
            int m = f >> 3, kv = f & 7;
            float4 va = *(const float4*)&g_cur[(size_t)(m0 + m) * Dd + k0 + kv * 4];
            Xs[kv * 4 + 0][m] = va.x;
            Xs[kv * 4 + 1][m] = va.y;
            Xs[kv * 4 + 2][m] = va.z;
            Xs[kv * 4 + 3][m] = va.w;
        }
        #pragma unroll
        for (int r = 0; r < 4; r++) {
            int f = t + r * 128;
            int n = f >> 3, kv = f & 7;
            float4 vb = *(const float4*)&B[(size_t)n * Dd + k0 + kv * 4];
            Ws[kv * 4 + 0][n] = vb.x;
            Ws[kv * 4 + 1][n] = vb.y;
            Ws[kv * 4 + 2][n] = vb.z;
            Ws[kv * 4 + 3][n] = vb.w;
        }
        __syncthreads();

        #pragma unroll
        for (int k = 0; k < 32; k++) {
            float4 a4 = *(const float4*)&Xs[k][ty * 4];
            float4 b4 = *(const float4*)&Ws[k][tx * 4];
            float a[4] = {a4.x, a4.y, a4.z, a4.w};
            float b[4] = {b4.x, b4.y, b4.z, b4.w};
            #pragma unroll
            for (int i = 0; i < 4; i++)
                #pragma unroll
                for (int j = 0; j < 4; j++)
                    acc[i][j] = fmaf(a[i], b[j], acc[i][j]);
        }
        __syncthreads();
    }

    #pragma unroll
    for (int i = 0; i < 4; i++) {
        float4 o = make_float4(acc[i][0], acc[i][1], acc[i][2], acc[i][3]);
        *(float4*)&C[(size_t)(m0 + ty * 4 + i) * DHh + tx * 4] = o;
    }
}

// ---------------- reduce 4 partials -> g_q/g_k/g_v ------------------------------
// grid (Sq*DHh/4/256, 3), block 256
__global__ void qkv_reduce()
{
    const int sel = blockIdx.y;
    const int i = blockIdx.x * 256 + threadIdx.x;   // float4 index
    float4 a = ((const float4*)&g_part[sel][0][0])[i];
    float4 b = ((const float4*)&g_part[sel][1][0])[i];
    float4 c = ((const float4*)&g_part[sel][2][0])[i];
    float4 d = ((const float4*)&g_part[sel][3][0])[i];
    float4 o;
    o.x = (a.x + b.x) + (c.x + d.x);
    o.y = (a.y + b.y) + (c.y + d.y);
    o.z = (a.z + b.z) + (c.z + d.z);
    o.w = (a.w + b.w) + (c.w + d.w);
    float* out = (sel == 0 ? g_q : sel == 1 ? g_k : g_v);
    ((float4*)out)[i] = o;
}

// ---------------- flash-style windowed attention (R3 proven) --------------------
#define KEXT 288
#define KP   68
#define PP   292

__global__ __launch_bounds__(256) void attn_flash()
{
    extern __shared__ float sm[];
    float* Ks = sm;                         // [288][68]
    float* Vs = sm + KEXT * KP;             // [288][68]
    float* Ps = sm + 2 * KEXT * KP;         // [16][292]
    float* Qs = Ps + 16 * PP;               // [16][64]
    float* Rs = sm;                         // partials, reuse Ks region

    const int t  = threadIdx.x;             // 256
    const int j0 = blockIdx.x * 16;
    const int kb = j0 - CWw;

    for (int f = t; f < KEXT * 16; f += 256) {
        int kk = f >> 4, d4 = f & 15;
        int gk = kb + kk;
        float4 kv = make_float4(0.f, 0.f, 0.f, 0.f);
        float4 vv = kv;
        if (gk >= 0 && gk < Sq) {
            kv = ((const float4*)&g_k[(size_t)gk * DHh])[d4];
            vv = ((const float4*)&g_v[(size_t)gk * DHh])[d4];
        }
        *(float4*)&Ks[kk * KP + d4 * 4] = kv;
        *(float4*)&Vs[kk * KP + d4 * 4] = vv;
    }
    {
        int q = t >> 4, d4 = t & 15;
        ((float4*)&Qs[q * DHh])[d4] = ((const float4*)&g_q[(size_t)(j0 + q) * DHh])[d4];
    }
    __syncthreads();

    const int w    = t >> 5;
    const int lane = t & 31;

    const int q0 = 2 * w, q1 = 2 * w + 1;
    float a0[9] = {}, a1[9] = {};
    #pragma unroll
    for (int d4 = 0; d4 < 16; d4++) {
        float4 qa = *(const float4*)&Qs[q0 * DHh + d4 * 4];
        float4 qb = *(const float4*)&Qs[q1 * DHh + d4 * 4];
        #pragma unroll
        for (int jj = 0; jj < 9; jj++) {
            const float4 kv = *(const float4*)&Ks[(lane + 32 * jj) * KP + d4 * 4];
            a0[jj] = fmaf(kv.x, qa.x, fmaf(kv.y, qa.y, fmaf(kv.z, qa.z, fmaf(kv.w, qa.w, a0[jj]))));
            a1[jj] = fmaf(kv.x, qb.x, fmaf(kv.y, qb.y, fmaf(kv.z, qb.z, fmaf(kv.w, qb.w, a1[jj]))));
        }
    }

    float m0 = -1e30f, m1 = -1e30f;
    #pragma unroll
    for (int jj = 0; jj < 9; jj++) {
        int kk = lane + 32 * jj;
        int gk = kb + kk;
        bool gok = (gk >= 0) && (gk < Sq);
        bool v0 = gok && (kk >= q0) && (kk < q0 + 256);
        bool v1 = gok && (kk >= q1) && (kk < q1 + 256);
        a0[jj] = v0 ? a0[jj] * 0.125f : -1e30f;
        a1[jj] = v1 ? a1[jj] * 0.125f : -1e30f;
        m0 = fmaxf(m0, a0[jj]);
        m1 = fmaxf(m1, a1[jj]);
    }
    #pragma unroll
    for (int o = 16; o; o >>= 1) {
        m0 = fmaxf(m0, __shfl_xor_sync(0xffffffffu, m0, o));
        m1 = fmaxf(m1, __shfl_xor_sync(0xffffffffu, m1, o));
    }
    float s0 = 0.f, s1 = 0.f;
    #pragma unroll
    for (int jj = 0; jj < 9; jj++) {
        a0[jj] = __expf(a0[jj] - m0);
        a1[jj] = __expf(a1[jj] - m1);
        s0 += a0[jj];
        s1 += a1[jj];
    }
    #pragma unroll
    for (int o = 16; o; o >>= 1) {
        s0 += __shfl_xor_sync(0xffffffffu, s0, o);
        s1 += __shfl_xor_sync(0xffffffffu, s1, o);
    }
    const float i0 = 1.f / s0, i1 = 1.f / s1;
    #pragma unroll
    for (int jj = 0; jj < 9; jj++) {
        Ps[q0 * PP + lane + 32 * jj] = a0[jj] * i0;
        Ps[q1 * PP + lane + 32 * jj] = a1[jj] * i1;
    }
    __syncthreads();

    const int qh = (lane >> 4) * 8;
    const int d4 = lane & 15;
    float4 r[8] = {};
    for (int i = 0; i < 36; i++) {
        int kk = w * 36 + i;
        float4 v4 = *(const float4*)&Vs[kk * KP + d4 * 4];
        #pragma unroll
        for (int qi = 0; qi < 8; qi++) {
            float p = Ps[(qh + qi) * PP + kk];
            r[qi].x = fmaf(p, v4.x, r[qi].x);
            r[qi].y = fmaf(p, v4.y, r[qi].y);
            r[qi].z = fmaf(p, v4.z, r[qi].z);
            r[qi].w = fmaf(p, v4.w, r[qi].w);
        }
    }
    #pragma unroll
    for (int qi = 0; qi < 8; qi++)
        *(float4*)&Rs[(w * 16 + qh + qi) * DHh + d4 * 4] = r[qi];
    __syncthreads();

    #pragma unroll
    for (int ii = 0; ii < 4; ii++) {
        int idx = t + 256 * ii;
        int q = idx >> 6, d = idx & 63;
        float s = 0.f;
        #pragma unroll
        for (int ww = 0; ww < 8; ww++) s += Rs[(ww * 16 + q) * DHh + d];
        g_delta[(size_t)(j0 + q) * DHh + d] = s;
    }
}

// ---------------- fused up-projection + residual + renorm (R3 proven) -----------
#define WP 516

__global__ __launch_bounds__(256) void upnorm_kernel(const float* __restrict__ Wvu,
                                                     int h, int last,
                                                     float* __restrict__ out)
{
    extern __shared__ float sm[];
    float* Ws = sm;                 // [64][516]
    float* As = sm + 64 * WP;       // [16][64]

    const int t  = threadIdx.x;     // 256
    const int m0 = blockIdx.x * 16;
    const float* W = Wvu + (size_t)h * Dd * DHh;

    {
        int k4 = t >> 4;
        int nb = t & 15;
        for (int i = 0; i < 32; i++) {
            int n = nb + 16 * i;
            float4 wv = *(const float4*)&W[(size_t)n * DHh + k4 * 4];
            Ws[(4 * k4 + 0) * WP + n] = wv.x;
            Ws[(4 * k4 + 1) * WP + n] = wv.y;
            Ws[(4 * k4 + 2) * WP + n] = wv.z;
            Ws[(4 * k4 + 3) * WP + n] = wv.w;
        }
    }
    {
        int m = t >> 4, k4 = t & 15;
        ((float4*)&As[m * DHh])[k4] = ((const float4*)&g_delta[(size_t)(m0 + m) * DHh])[k4];
    }
    __syncthreads();

    const int w    = t >> 5;
    const int lane = t & 31;
    const int r0 = m0 + 2 * w, r1 = r0 + 1;

    float4 y0[4] = {}, y1[4] = {};
    for (int k = 0; k < DHh; k++) {
        float av0 = As[(2 * w) * DHh + k];
        float av1 = As[(2 * w + 1) * DHh + k];
        #pragma unroll
        for (int j = 0; j < 4; j++) {
            float4 wv = *(const float4*)&Ws[k * WP + 4 * (lane + 32 * j)];
            y0[j].x = fmaf(av0, wv.x, y0[j].x);
            y0[j].y = fmaf(av0, wv.y, y0[j].y);
            y0[j].z = fmaf(av0, wv.z, y0[j].z);
            y0[j].w = fmaf(av0, wv.w, y0[j].w);
            y1[j].x = fmaf(av1, wv.x, y1[j].x);
            y1[j].y = fmaf(av1, wv.y, y1[j].y);
            y1[j].z = fmaf(av1, wv.z, y1[j].z);
            y1[j].w = fmaf(av1, wv.w, y1[j].w);
        }
    }

    float4 c0[4], c1[4];
    #pragma unroll
    for (int j = 0; j < 4; j++) {
        c0[j] = ((const float4*)&g_cur[(size_t)r0 * Dd])[lane + 32 * j];
        c1[j] = ((const float4*)&g_cur[(size_t)r1 * Dd])[lane + 32 * j];
        y0[j].x += c0[j].x; y0[j].y += c0[j].y; y0[j].z += c0[j].z; y0[j].w += c0[j].w;
        y1[j].x += c1[j].x; y1[j].y += c1[j].y; y1[j].z += c1[j].z; y1[j].w += c1[j].w;
    }

    float t0 = 0.f, t1 = 0.f;
    #pragma unroll
    for (int j = 0; j < 4; j++) {
        t0 += y0[j].x + y0[j].y + y0[j].z + y0[j].w;
        t1 += y1[j].x + y1[j].y + y1[j].z + y1[j].w;
    }
    #pragma unroll
    for (int o = 16; o; o >>= 1) {
        t0 += __shfl_xor_sync(0xffffffffu, t0, o);
        t1 += __shfl_xor_sync(0xffffffffu, t1, o);
    }
    float im0 = 512.f / t0, im1 = 512.f / t1;
    #pragma unroll
    for (int j = 0; j < 4; j++) {
        y0[j].x *= im0; y0[j].y *= im0; y0[j].z *= im0; y0[j].w *= im0;
        y1[j].x *= im1; y1[j].y *= im1; y1[j].z *= im1; y1[j].w *= im1;
    }
    t0 = 0.f; t1 = 0.f;
    #pragma unroll
    for (int j = 0; j < 4; j++) {
        t0 += y0[j].x + y0[j].y + y0[j].z + y0[j].w;
        t1 += y1[j].x + y1[j].y + y1[j].z + y1[j].w;
    }
    #pragma unroll
    for (int o = 16; o; o >>= 1) {
        t0 += __shfl_xor_sync(0xffffffffu, t0, o);
        t1 += __shfl_xor_sync(0xffffffffu, t1, o);
    }
    float mu0 = t0 * (1.f / 512.f), mu1 = t1 * (1.f / 512.f);
    float v0 = 0.f, v1 = 0.f;
    #pragma unroll
    for (int j = 0; j < 4; j++) {
        y0[j].x -= mu0; y0[j].y -= mu0; y0[j].z -= mu0; y0[j].w -= mu0;
        y1[j].x -= mu1; y1[j].y -= mu1; y1[j].z -= mu1; y1[j].w -= mu1;
        v0 += y0[j].x*y0[j].x + y0[j].y*y0[j].y + y0[j].z*y0[j].z + y0[j].w*y0[j].w;
        v1 += y1[j].x*y1[j].x + y1[j].y*y1[j].y + y1[j].z*y1[j].z + y1[j].w*y1[j].w;
    }
    #pragma unroll
    for (int o = 16; o; o >>= 1) {
        v0 += __shfl_xor_sync(0xffffffffu, v0, o);
        v1 += __shfl_xor_sync(0xffffffffu, v1, o);
    }
    float is0 = rsqrtf(v0 * (1.f / 511.f));
    float is1 = rsqrtf(v1 * (1.f / 511.f));

    #pragma unroll
    for (int j = 0; j < 4; j++) {
        float4 n0, n1;
        n0.x = c0[j].x + y0[j].x * is0 + mu0;
        n0.y = c0[j].y + y0[j].y * is0 + mu0;
        n0.z = c0[j].z + y0[j].z * is0 + mu0;
        n0.w = c0[j].w + y0[j].w * is0 + mu0;
        n1.x = c1[j].x + y1[j].x * is1 + mu1;
        n1.y = c1[j].y + y1[j].y * is1 + mu1;
        n1.z = c1[j].z + y1[j].z * is1 + mu1;
        n1.w = c1[j].w + y1[j].w * is1 + mu1;
        ((float4*)&g_cur[(size_t)r0 * Dd])[lane + 32 * j] = n0;
        ((float4*)&g_cur[(size_t)r1 * Dd])[lane + 32 * j] = n1;
        if (last) {
            n0.x *= 0.125f; n0.y *= 0.125f; n0.z *= 0.125f; n0.w *= 0.125f;
            n1.x *= 0.125f; n1.y *= 0.125f; n1.z *= 0.125f; n1.w *= 0.125f;
            ((float4*)&out[(size_t)r0 * Dd])[lane + 32 * j] = n0;
            ((float4*)&out[(size_t)r1 * Dd])[lane + 32 * j] = n1;
        }
    }
}

// ---------------- launch ---------------------------------------------------------
extern "C" void kernel_launch(void* const* d_in, const int* in_sizes, int n_in,
                              void* d_out, int out_size)
{
    const float* x   = (const float*)d_in[0];
    const float* Wq  = (const float*)d_in[1];
    const float* Wk  = (const float*)d_in[2];
    const float* Wvd = (const float*)d_in[3];
    const float* Wvu = (const float*)d_in[4];
    float* out = (float*)d_out;

    const int attn_smem = (2 * KEXT * KP + 16 * PP + 16 * DHh) * 4;   // 179456
    const int up_smem   = (64 * WP + 16 * DHh) * 4;                   // 136192
    cudaFuncSetAttribute(attn_flash, cudaFuncAttributeMaxDynamicSharedMemorySize, attn_smem);
    cudaFuncSetAttribute(upnorm_kernel, cudaFuncAttributeMaxDynamicSharedMemorySize, up_smem);

    init_kernel<<<(Sq * Dd / 4) / 256, 256>>>((const float4*)x);
    for (int h = 0; h < Hh; h++) {
        qkv_partial<<<dim3(Sq / 32, 3, NSPLIT), 128>>>(Wq, Wk, Wvd, h);
        qkv_reduce<<<dim3(Sq * DHh / 4 / 256, 3), 256>>>();
        attn_flash<<<Sq / 16, 256, attn_smem>>>();
        upnorm_kernel<<<Sq / 16, 256, up_smem>>>(Wvu, h, h == Hh - 1 ? 1 : 0, out);
    }
}